// round 16
// baseline (speedup 1.0000x reference)
#include <cuda_runtime.h>
#include <cstdint>

#define BATCH 32
#define DIM   256
#define HW    56
#define SP    (HW*HW)
#define PW    7
#define PP    49
#define DD    3
#define N1    8
#define N2    8
#define NWIN  64
#define HEADS 8
#define DH    32
#define INNER 256
#define QKV_N 768
#define M_TOTAL (BATCH*NWIN*PP)

#define PADW 136

__device__ float    g_qkv[(size_t)M_TOTAL * QKV_N];
__device__ uint32_t g_att32[(size_t)M_TOTAL * INNER];
__device__ uint32_t g_wqkv32[DIM * QKV_N];
__device__ uint32_t g_wout32[INNER * DIM];

typedef unsigned long long u64;

__device__ __forceinline__ uint32_t f2tf32(float f) {
    uint32_t r; asm("cvt.rna.tf32.f32 %0, %1;" : "=r"(r) : "f"(f)); return r;
}
__device__ __forceinline__ void mma_tf32(float* d, const uint32_t* a, const uint32_t* b) {
    asm volatile(
        "mma.sync.aligned.m16n8k8.row.col.f32.tf32.tf32.f32 "
        "{%0,%1,%2,%3}, {%4,%5,%6,%7}, {%8,%9}, {%0,%1,%2,%3};"
        : "+f"(d[0]), "+f"(d[1]), "+f"(d[2]), "+f"(d[3])
        : "r"(a[0]), "r"(a[1]), "r"(a[2]), "r"(a[3]), "r"(b[0]), "r"(b[1]));
}

__device__ __forceinline__ int row_to_off(int r) {
    int bi  = r / (NWIN * PP);
    int rem = r % (NWIN * PP);
    int w   = rem / PP;
    int t   = rem % PP;
    int n1i = w / N2, n2i = w % N2;
    int py  = t / PW, px  = t % PW;
    int hh  = (n1i * PW + py + DD) % HW;
    int ww  = (n2i * PW + px + DD) % HW;
    return bi * DIM * SP + hh * HW + ww;
}

// ---------------------------------------------------------------------------
__global__ void prep_w(const float* __restrict__ wqkv, const float* __restrict__ wout) {
    const int t1 = DIM * QKV_N;
    const int t2 = INNER * DIM;
    for (int i = blockIdx.x * blockDim.x + threadIdx.x; i < t1 + t2;
         i += gridDim.x * blockDim.x) {
        if (i < t1) g_wqkv32[i] = f2tf32(wqkv[i]);
        else        g_wout32[i - t1] = f2tf32(wout[i - t1]);
    }
}

// ---------------------------------------------------------------------------
// Kernel 1: qkv GEMM (unchanged, measured 363 us)
// ---------------------------------------------------------------------------
__global__ void __launch_bounds__(128, 2) qkv_gemm(const float* __restrict__ x) {
    __shared__ uint32_t As[2][16][PADW];
    __shared__ uint32_t Bs[2][16][PADW];

    const int m0  = blockIdx.y * 128;
    const int n0  = blockIdx.x * 128;
    const int tid = threadIdx.x;

    const int lane = tid & 31;
    const int wid  = tid >> 5;
    const int mb   = (wid & 1) * 64;
    const int nb   = (wid >> 1) * 64;
    const int tg   = lane >> 2;
    const int tq   = lane & 3;

    const float*    arow = x + row_to_off(m0 + tid);
    const uint32_t* brow = g_wqkv32 + n0 + tid;

    float d[4][8][4] = {};
    float    a_reg[16];
    uint32_t b_reg[16];

    #pragma unroll
    for (int i = 0; i < 16; i++) {
        a_reg[i] = arow[i * SP];
        b_reg[i] = brow[i * QKV_N];
    }
    #pragma unroll
    for (int i = 0; i < 16; i++) {
        As[0][i][tid] = f2tf32(a_reg[i]);
        Bs[0][i][tid] = b_reg[i];
    }
    __syncthreads();

    for (int c = 0; c < 16; c++) {
        const int cur = c & 1;
        if (c < 15) {
            const int kb = (c + 1) * 16;
            #pragma unroll
            for (int i = 0; i < 16; i++) {
                a_reg[i] = arow[(kb + i) * SP];
                b_reg[i] = brow[(kb + i) * QKV_N];
            }
        }
        #pragma unroll
        for (int s = 0; s < 2; s++) {
            uint32_t a[4][4], b[8][2];
            #pragma unroll
            for (int am = 0; am < 4; am++) {
                int r = mb + am * 16 + tg;
                a[am][0] = As[cur][s * 8 + tq][r];
                a[am][1] = As[cur][s * 8 + tq][r + 8];
                a[am][2] = As[cur][s * 8 + tq + 4][r];
                a[am][3] = As[cur][s * 8 + tq + 4][r + 8];
            }
            #pragma unroll
            for (int an = 0; an < 8; an++) {
                int cc = nb + an * 8 + tg;
                b[an][0] = Bs[cur][s * 8 + tq][cc];
                b[an][1] = Bs[cur][s * 8 + tq + 4][cc];
            }
            #pragma unroll
            for (int am = 0; am < 4; am++)
                #pragma unroll
                for (int an = 0; an < 8; an++)
                    mma_tf32(d[am][an], a[am], b[an]);
        }
        if (c < 15) {
            const int nxt = cur ^ 1;
            #pragma unroll
            for (int i = 0; i < 16; i++) {
                As[nxt][i][tid] = f2tf32(a_reg[i]);
                Bs[nxt][i][tid] = b_reg[i];
            }
        }
        __syncthreads();
    }

    #pragma unroll
    for (int am = 0; am < 4; am++) {
        size_t r0 = (size_t)(m0 + mb + am * 16 + tg) * QKV_N;
        size_t r1 = r0 + 8 * QKV_N;
        #pragma unroll
        for (int an = 0; an < 8; an++) {
            int c = n0 + nb + an * 8 + 2 * tq;
            *(float2*)&g_qkv[r0 + c] = make_float2(d[am][an][0], d[am][an][1]);
            *(float2*)&g_qkv[r1 + c] = make_float2(d[am][an][2], d[am][an][3]);
        }
    }
}

// ---------------------------------------------------------------------------
// Kernel 2: attention via tensor cores (R14 structure, parallel softmax)
// ---------------------------------------------------------------------------
__global__ void __launch_bounds__(256) attn_kernel(const float* __restrict__ pos,
                                                   float* __restrict__ attn_out) {
    const int bid  = blockIdx.x;
    const int head = bid % HEADS;
    const int bw   = bid / HEADS;
    const int w    = bw % NWIN;
    const int bi   = bw / NWIN;
    const int tid  = threadIdx.x;
    const int lane = tid & 31;
    const int wid  = tid >> 5;
    const int tg   = lane >> 2;
    const int tq   = lane & 3;

    __shared__ uint32_t qT[DH][72];
    __shared__ uint32_t kT[DH][56];
    __shared__ uint32_t v[56][40];
    __shared__ uint32_t dotsT[56][72];
    __shared__ float poss[169];
    __shared__ float cpart[PP][7];
    __shared__ float rowinv[PP];

    const float* base = g_qkv + (size_t)(bi * NWIN + w) * PP * QKV_N + head * DH;
    for (int idx = tid; idx < PP * 8; idx += 256) {
        int t = idx >> 3, c = idx & 7;
        const float* rowp = base + (size_t)t * QKV_N + c * 4;
        float4 qf = *(const float4*)(rowp);
        float4 kf = *(const float4*)(rowp + INNER);
        float4 vf = *(const float4*)(rowp + 2 * INNER);
        int d = c * 4;
        qT[d][t] = f2tf32(qf.x); qT[d + 1][t] = f2tf32(qf.y);
        qT[d + 2][t] = f2tf32(qf.z); qT[d + 3][t] = f2tf32(qf.w);
        kT[d][t] = f2tf32(kf.x); kT[d + 1][t] = f2tf32(kf.y);
        kT[d + 2][t] = f2tf32(kf.z); kT[d + 3][t] = f2tf32(kf.w);
        v[t][d]     = f2tf32(vf.x); v[t][d + 1] = f2tf32(vf.y);
        v[t][d + 2] = f2tf32(vf.z); v[t][d + 3] = f2tf32(vf.w);
    }
    for (int idx = tid; idx < 7 * 40; idx += 256)  v[49 + idx / 40][idx % 40] = 0u;
    for (int idx = tid; idx < 7 * 72; idx += 256)  dotsT[49 + idx / 72][idx % 72] = 0u;
    for (int idx = tid; idx < 169; idx += 256)     poss[idx] = pos[idx];
    __syncthreads();

    const bool m_ul = (w >= NWIN - N2);
    const bool m_lr = (w >= NWIN - N1 - 1) && ((w - (NWIN - N1 - 1)) % N1 == 0);
    const float NEG = -1e30f;
    const float scale = 0.17677669529663687f;

    // ---- QK: warps 0-6 ----
    if (wid < 7) {
        const int na = wid;
        const int j0 = na * 8 + 2 * tq;
        float dreg[4][4] = {};
        #pragma unroll
        for (int s = 0; s < 4; s++) {
            uint32_t b[2];
            b[0] = kT[s * 8 + tq][na * 8 + tg];
            b[1] = kT[s * 8 + tq + 4][na * 8 + tg];
            #pragma unroll
            for (int ma = 0; ma < 4; ma++) {
                int r = ma * 16 + tg;
                uint32_t a[4];
                a[0] = qT[s * 8 + tq][r];
                a[1] = qT[s * 8 + tq][r + 8];
                a[2] = qT[s * 8 + tq + 4][r];
                a[3] = qT[s * 8 + tq + 4][r + 8];
                mma_tf32(dreg[ma], a, b);
            }
        }
        #pragma unroll
        for (int ma = 0; ma < 4; ma++) {
            int r0 = ma * 16 + tg;
            int r1 = r0 + 8;
            float vals[2][2] = {{dreg[ma][0], dreg[ma][1]}, {dreg[ma][2], dreg[ma][3]}};
            float rmax[2];
            #pragma unroll
            for (int h = 0; h < 2; h++) {
                int i = h ? r1 : r0;
                float cm = NEG;
                if (i < PP) {
                    int iy = i / PW, ix = i % PW;
                    #pragma unroll
                    for (int jj = 0; jj < 2; jj++) {
                        int j = j0 + jj;
                        float val = NEG;
                        if (j < PP) {
                            int jy = j / PW, jx = j % PW;
                            val = vals[h][jj] * scale + poss[(jy - iy + 6) * 13 + (jx - ix + 6)];
                            if (m_ul && ((iy >= 4) != (jy >= 4))) val = NEG;
                            if (m_lr && ((ix >= 4) != (jx >= 4))) val = NEG;
                            dotsT[j][i] = __float_as_uint(val);
                            cm = fmaxf(cm, val);
                        }
                    }
                }
                rmax[h] = cm;
            }
            #pragma unroll
            for (int h = 0; h < 2; h++) {
                rmax[h] = fmaxf(rmax[h], __shfl_xor_sync(0xffffffffu, rmax[h], 1));
                rmax[h] = fmaxf(rmax[h], __shfl_xor_sync(0xffffffffu, rmax[h], 2));
            }
            if (tq == 0) {
                if (r0 < PP) cpart[r0][na] = rmax[0];
                if (r1 < PP) cpart[r1][na] = rmax[1];
            }
        }
    }
    __syncthreads();

    // ---- softmax: 4 threads per row (196 threads = 49 complete quads) ----
    if (tid < 196) {
        int i = tid >> 2, part = tid & 3;
        float mx = cpart[i][0];
        #pragma unroll
        for (int c = 1; c < 7; c++) mx = fmaxf(mx, cpart[i][c]);
        int j0 = part * 13;
        int jn = (part == 3) ? 10 : 13;
        float s = 0.f;
        for (int jj = 0; jj < jn; jj++) {
            int j = j0 + jj;
            float e = __expf(__uint_as_float(dotsT[j][i]) - mx);
            dotsT[j][i] = f2tf32(e);
            s += e;
        }
        unsigned gmask = 0xFu << (lane & 28);
        s += __shfl_xor_sync(gmask, s, 1);
        s += __shfl_xor_sync(gmask, s, 2);
        if (part == 0) rowinv[i] = 1.0f / s;
    }
    __syncthreads();

    // ---- AV: 8 warps ----
    {
        const int na = wid & 3;
        const int mh = wid >> 2;
        uint32_t* ob = g_att32 + (size_t)(bi * NWIN + w) * PP * INNER + head * DH;
        float dreg[2][4] = {};
        #pragma unroll
        for (int t = 0; t < 7; t++) {
            uint32_t b[2];
            b[0] = v[t * 8 + tq][na * 8 + tg];
            b[1] = v[t * 8 + tq + 4][na * 8 + tg];
            #pragma unroll
            for (int mi = 0; mi < 2; mi++) {
                int r = (mh * 2 + mi) * 16 + tg;
                uint32_t a[4];
                a[0] = dotsT[t * 8 + tq][r];
                a[1] = dotsT[t * 8 + tq][r + 8];
                a[2] = dotsT[t * 8 + tq + 4][r];
                a[3] = dotsT[t * 8 + tq + 4][r + 8];
                mma_tf32(dreg[mi], a, b);
            }
        }
        #pragma unroll
        for (int mi = 0; mi < 2; mi++) {
            int r0 = (mh * 2 + mi) * 16 + tg;
            int dcol = na * 8 + 2 * tq;
            if (r0 < PP) {
                float inv = rowinv[r0];
                uint2 o;
                o.x = f2tf32(dreg[mi][0] * inv);
                o.y = f2tf32(dreg[mi][1] * inv);
                *(uint2*)&ob[(size_t)r0 * INNER + dcol] = o;
            }
            int r1 = r0 + 8;
            if (r1 < PP) {
                float inv = rowinv[r1];
                uint2 o;
                o.x = f2tf32(dreg[mi][2] * inv);
                o.y = f2tf32(dreg[mi][3] * inv);
                *(uint2*)&ob[(size_t)r1 * INNER + dcol] = o;
            }
        }
    }

    float* ao = attn_out + (size_t)bid * (PP * PP);
    for (int idx = tid; idx < PP * PP; idx += 256) {
        int i = idx / PP, j = idx % PP;
        ao[idx] = __uint_as_float(dotsT[j][i]) * rowinv[i];
    }
}

// ---------------------------------------------------------------------------
// Kernel 3: out GEMM — 256 threads, 8 warps of 64x32, double-buffered
// ---------------------------------------------------------------------------
__global__ void __launch_bounds__(256, 2) out_gemm(const float* __restrict__ bout,
                                                   float* __restrict__ out) {
    __shared__ union U {
        struct { uint32_t As[2][16][PADW]; uint32_t Bs[2][16][PADW]; } mm;
        float sbuf[128][65];
        __device__ U() {}
    } sh;
    __shared__ int   rowoff[128];
    __shared__ float bout_s[128];

    const int m0  = blockIdx.y * 128;
    const int n0  = blockIdx.x * 128;
    const int tid = threadIdx.x;

    if (tid < 128) {
        rowoff[tid] = row_to_off(m0 + tid);
        bout_s[tid] = bout[n0 + tid];
    }

    const int lane = tid & 31;
    const int wid  = tid >> 5;          // 0..7
    const int mb   = (wid & 1) * 64;
    const int nb   = (wid >> 1) * 32;   // 0,32,64,96
    const int tg   = lane >> 2;
    const int tq   = lane & 3;

    const int lm  = tid & 127;
    const int lk0 = tid >> 7;           // 0..1

    const uint32_t* arow = g_att32 + (size_t)(m0 + lm) * INNER + lk0 * 8;
    const uint32_t* brow = g_wout32 + n0 + lm;

    float d[4][4][4] = {};
    uint32_t a_reg[8], b_reg[8];

    // preload chunk 0
    *(uint4*)&a_reg[0] = *(const uint4*)(arow);
    *(uint4*)&a_reg[4] = *(const uint4*)(arow + 4);
    #pragma unroll
    for (int i = 0; i < 8; i++) b_reg[i] = brow[(lk0 + 2 * i) * DIM];
    #pragma unroll
    for (int i = 0; i < 8; i++) {
        sh.mm.As[0][lk0 * 8 + i][lm] = a_reg[i];
        sh.mm.Bs[0][lk0 + 2 * i][lm] = b_reg[i];
    }
    __syncthreads();

    for (int c = 0; c < 16; c++) {
        const int cur = c & 1;
        if (c < 15) {
            const int kb = (c + 1) * 16;
            *(uint4*)&a_reg[0] = *(const uint4*)(arow + kb);
            *(uint4*)&a_reg[4] = *(const uint4*)(arow + kb + 4);
            #pragma unroll
            for (int i = 0; i < 8; i++) b_reg[i] = brow[(kb + lk0 + 2 * i) * DIM];
        }
        #pragma unroll
        for (int s = 0; s < 2; s++) {
            uint32_t a[4][4], b[4][2];
            #pragma unroll
            for (int am = 0; am < 4; am++) {
                int r = mb + am * 16 + tg;
                a[am][0] = sh.mm.As[cur][s * 8 + tq][r];
                a[am][1] = sh.mm.As[cur][s * 8 + tq][r + 8];
                a[am][2] = sh.mm.As[cur][s * 8 + tq + 4][r];
                a[am][3] = sh.mm.As[cur][s * 8 + tq + 4][r + 8];
            }
            #pragma unroll
            for (int an = 0; an < 4; an++) {
                int cc = nb + an * 8 + tg;
                b[an][0] = sh.mm.Bs[cur][s * 8 + tq][cc];
                b[an][1] = sh.mm.Bs[cur][s * 8 + tq + 4][cc];
            }
            #pragma unroll
            for (int am = 0; am < 4; am++)
                #pragma unroll
                for (int an = 0; an < 4; an++)
                    mma_tf32(d[am][an], a[am], b[an]);
        }
        if (c < 15) {
            const int nxt = cur ^ 1;
            #pragma unroll
            for (int i = 0; i < 8; i++) {
                sh.mm.As[nxt][lk0 * 8 + i][lm] = a_reg[i];
                sh.mm.Bs[nxt][lk0 + 2 * i][lm] = b_reg[i];
            }
        }
        __syncthreads();
    }

    // Epilogue: two half-passes through 128x65 staging buffer
    const int half_w = wid >> 2;   // nb 0/32 -> 0 ; 64/96 -> 1
    #pragma unroll
    for (int half = 0; half < 2; half++) {
        if (half_w == half) {
            #pragma unroll
            for (int am = 0; am < 4; am++) {
                int r0 = mb + am * 16 + tg;
                #pragma unroll
                for (int an = 0; an < 4; an++) {
                    int c = (nb & 63) + an * 8 + 2 * tq;
                    sh.sbuf[r0][c]         = d[am][an][0];
                    sh.sbuf[r0][c + 1]     = d[am][an][1];
                    sh.sbuf[r0 + 8][c]     = d[am][an][2];
                    sh.sbuf[r0 + 8][c + 1] = d[am][an][3];
                }
            }
        }
        __syncthreads();
        #pragma unroll
        for (int it = 0; it < 32; it++) {
            int flat = it * 256 + tid;
            int m = flat & 127;
            int cc = flat >> 7;          // 0..63
            int col = half * 64 + cc;
            out[rowoff[m] + (n0 + col) * SP] = sh.sbuf[m][cc] + bout_s[col];
        }
        __syncthreads();
    }
}

// ---------------------------------------------------------------------------
extern "C" void kernel_launch(void* const* d_in, const int* in_sizes, int n_in,
                              void* d_out, int out_size) {
    const float* x    = (const float*)d_in[0];
    const float* pos  = (const float*)d_in[1];
    const float* wqkv = (const float*)d_in[2];
    const float* wout = (const float*)d_in[3];
    const float* bout = (const float*)d_in[4];

    float* out      = (float*)d_out;
    float* attn_out = out + (size_t)BATCH * DIM * SP;

    prep_w<<<256, 256>>>(wqkv, wout);

    dim3 g1(QKV_N / 128, M_TOTAL / 128);
    qkv_gemm<<<g1, 128>>>(x);

    attn_kernel<<<BATCH * NWIN * HEADS, 256>>>(pos, attn_out);

    dim3 g3(DIM / 128, M_TOTAL / 128);
    out_gemm<<<g3, 256>>>(bout, out);
}

// round 17
// speedup vs baseline: 1.0409x; 1.0409x over previous
#include <cuda_runtime.h>
#include <cstdint>

#define BATCH 32
#define DIM   256
#define HW    56
#define SP    (HW*HW)
#define PW    7
#define PP    49
#define DD    3
#define N1    8
#define N2    8
#define NWIN  64
#define HEADS 8
#define DH    32
#define INNER 256
#define QKV_N 768
#define M_TOTAL (BATCH*NWIN*PP)

#define PADW 136
#define PAD2 132   // uint2 stride: 264 words % 32 == 8 -> conflict-free

__device__ float    g_qkv[(size_t)M_TOTAL * QKV_N];
__device__ uint32_t g_att32[(size_t)M_TOTAL * INNER];
__device__ uint32_t g_wqkv32[DIM * QKV_N];
__device__ uint32_t g_wout32[INNER * DIM];

typedef unsigned long long u64;

__device__ __forceinline__ uint32_t f2tf32(float f) {
    uint32_t r; asm("cvt.rna.tf32.f32 %0, %1;" : "=r"(r) : "f"(f)); return r;
}
__device__ __forceinline__ void mma_tf32(float* d, const uint32_t* a, const uint32_t* b) {
    asm volatile(
        "mma.sync.aligned.m16n8k8.row.col.f32.tf32.tf32.f32 "
        "{%0,%1,%2,%3}, {%4,%5,%6,%7}, {%8,%9}, {%0,%1,%2,%3};"
        : "+f"(d[0]), "+f"(d[1]), "+f"(d[2]), "+f"(d[3])
        : "r"(a[0]), "r"(a[1]), "r"(a[2]), "r"(a[3]), "r"(b[0]), "r"(b[1]));
}

__device__ __forceinline__ int row_to_off(int r) {
    int bi  = r / (NWIN * PP);
    int rem = r % (NWIN * PP);
    int w   = rem / PP;
    int t   = rem % PP;
    int n1i = w / N2, n2i = w % N2;
    int py  = t / PW, px  = t % PW;
    int hh  = (n1i * PW + py + DD) % HW;
    int ww  = (n2i * PW + px + DD) % HW;
    return bi * DIM * SP + hh * HW + ww;
}

// ---------------------------------------------------------------------------
__global__ void prep_w(const float* __restrict__ wqkv, const float* __restrict__ wout) {
    const int t1 = DIM * QKV_N;
    const int t2 = INNER * DIM;
    for (int i = blockIdx.x * blockDim.x + threadIdx.x; i < t1 + t2;
         i += gridDim.x * blockDim.x) {
        if (i < t1) g_wqkv32[i] = f2tf32(wqkv[i]);
        else        g_wout32[i - t1] = f2tf32(wout[i - t1]);
    }
}

// ---------------------------------------------------------------------------
// Kernel 1: qkv GEMM — packed uint2 fragments (1 LDS.64 per fragment pair)
// 128x128 tile, 4 warps of 64x64, double-buffered, 2 CTAs/SM
// ---------------------------------------------------------------------------
__global__ void __launch_bounds__(128, 2) qkv_gemm(const float* __restrict__ x) {
    __shared__ uint2 Apk[2][8][PAD2];   // [buf][kp][m], kp = s*4+tq -> (k, k+4)
    __shared__ uint2 Bpk[2][8][PAD2];   // [buf][kp][n]

    const int m0  = blockIdx.y * 128;
    const int n0  = blockIdx.x * 128;
    const int tid = threadIdx.x;

    const int lane = tid & 31;
    const int wid  = tid >> 5;
    const int mb   = (wid & 1) * 64;
    const int nb   = (wid >> 1) * 64;
    const int tg   = lane >> 2;
    const int tq   = lane & 3;

    const float*    arow = x + row_to_off(m0 + tid);
    const uint32_t* brow = g_wqkv32 + n0 + tid;

    float d[4][8][4] = {};
    float    a_reg[16];
    uint32_t b_reg[16];

    #pragma unroll
    for (int i = 0; i < 16; i++) {
        a_reg[i] = arow[i * SP];
        b_reg[i] = brow[i * QKV_N];
    }
    #pragma unroll
    for (int kp = 0; kp < 8; kp++) {
        int klo = (kp >> 2) * 8 + (kp & 3);
        Apk[0][kp][tid] = make_uint2(f2tf32(a_reg[klo]), f2tf32(a_reg[klo + 4]));
        Bpk[0][kp][tid] = make_uint2(b_reg[klo], b_reg[klo + 4]);
    }
    __syncthreads();

    for (int c = 0; c < 16; c++) {
        const int cur = c & 1;
        if (c < 15) {
            const int kb = (c + 1) * 16;
            #pragma unroll
            for (int i = 0; i < 16; i++) {
                a_reg[i] = arow[(kb + i) * SP];
                b_reg[i] = brow[(kb + i) * QKV_N];
            }
        }
        #pragma unroll
        for (int s = 0; s < 2; s++) {
            const int kp = s * 4 + tq;
            uint32_t a[4][4], b[8][2];
            #pragma unroll
            for (int am = 0; am < 4; am++) {
                int r = mb + am * 16 + tg;
                uint2 p0 = Apk[cur][kp][r];
                uint2 p1 = Apk[cur][kp][r + 8];
                a[am][0] = p0.x; a[am][2] = p0.y;
                a[am][1] = p1.x; a[am][3] = p1.y;
            }
            #pragma unroll
            for (int an = 0; an < 8; an++) {
                uint2 pb = Bpk[cur][kp][nb + an * 8 + tg];
                b[an][0] = pb.x; b[an][1] = pb.y;
            }
            #pragma unroll
            for (int am = 0; am < 4; am++)
                #pragma unroll
                for (int an = 0; an < 8; an++)
                    mma_tf32(d[am][an], a[am], b[an]);
        }
        if (c < 15) {
            const int nxt = cur ^ 1;
            #pragma unroll
            for (int kp = 0; kp < 8; kp++) {
                int klo = (kp >> 2) * 8 + (kp & 3);
                Apk[nxt][kp][tid] = make_uint2(f2tf32(a_reg[klo]), f2tf32(a_reg[klo + 4]));
                Bpk[nxt][kp][tid] = make_uint2(b_reg[klo], b_reg[klo + 4]);
            }
        }
        __syncthreads();
    }

    #pragma unroll
    for (int am = 0; am < 4; am++) {
        size_t r0 = (size_t)(m0 + mb + am * 16 + tg) * QKV_N;
        size_t r1 = r0 + 8 * QKV_N;
        #pragma unroll
        for (int an = 0; an < 8; an++) {
            int c = n0 + nb + an * 8 + 2 * tq;
            *(float2*)&g_qkv[r0 + c] = make_float2(d[am][an][0], d[am][an][1]);
            *(float2*)&g_qkv[r1 + c] = make_float2(d[am][an][2], d[am][an][3]);
        }
    }
}

// ---------------------------------------------------------------------------
// Kernel 2: attention via tensor cores (R14-measured version, unchanged)
// ---------------------------------------------------------------------------
__global__ void __launch_bounds__(256) attn_kernel(const float* __restrict__ pos,
                                                   float* __restrict__ attn_out) {
    const int bid  = blockIdx.x;
    const int head = bid % HEADS;
    const int bw   = bid / HEADS;
    const int w    = bw % NWIN;
    const int bi   = bw / NWIN;
    const int tid  = threadIdx.x;
    const int lane = tid & 31;
    const int wid  = tid >> 5;
    const int tg   = lane >> 2;
    const int tq   = lane & 3;

    __shared__ uint32_t qT[DH][72];
    __shared__ uint32_t kT[DH][56];
    __shared__ uint32_t v[56][40];
    __shared__ uint32_t dotsT[56][72];
    __shared__ float poss[169];
    __shared__ float cpart[PP][7];
    __shared__ float rowinv[PP];

    const float* base = g_qkv + (size_t)(bi * NWIN + w) * PP * QKV_N + head * DH;
    for (int idx = tid; idx < PP * 8; idx += 256) {
        int t = idx >> 3, c = idx & 7;
        const float* rowp = base + (size_t)t * QKV_N + c * 4;
        float4 qf = *(const float4*)(rowp);
        float4 kf = *(const float4*)(rowp + INNER);
        float4 vf = *(const float4*)(rowp + 2 * INNER);
        int d = c * 4;
        qT[d][t] = f2tf32(qf.x); qT[d + 1][t] = f2tf32(qf.y);
        qT[d + 2][t] = f2tf32(qf.z); qT[d + 3][t] = f2tf32(qf.w);
        kT[d][t] = f2tf32(kf.x); kT[d + 1][t] = f2tf32(kf.y);
        kT[d + 2][t] = f2tf32(kf.z); kT[d + 3][t] = f2tf32(kf.w);
        v[t][d]     = f2tf32(vf.x); v[t][d + 1] = f2tf32(vf.y);
        v[t][d + 2] = f2tf32(vf.z); v[t][d + 3] = f2tf32(vf.w);
    }
    for (int idx = tid; idx < 7 * 40; idx += 256)  v[49 + idx / 40][idx % 40] = 0u;
    for (int idx = tid; idx < 7 * 72; idx += 256)  dotsT[49 + idx / 72][idx % 72] = 0u;
    for (int idx = tid; idx < 169; idx += 256)     poss[idx] = pos[idx];
    __syncthreads();

    const bool m_ul = (w >= NWIN - N2);
    const bool m_lr = (w >= NWIN - N1 - 1) && ((w - (NWIN - N1 - 1)) % N1 == 0);
    const float NEG = -1e30f;
    const float scale = 0.17677669529663687f;

    if (wid < 7) {
        const int na = wid;
        const int j0 = na * 8 + 2 * tq;
        float dreg[4][4] = {};
        #pragma unroll
        for (int s = 0; s < 4; s++) {
            uint32_t b[2];
            b[0] = kT[s * 8 + tq][na * 8 + tg];
            b[1] = kT[s * 8 + tq + 4][na * 8 + tg];
            #pragma unroll
            for (int ma = 0; ma < 4; ma++) {
                int r = ma * 16 + tg;
                uint32_t a[4];
                a[0] = qT[s * 8 + tq][r];
                a[1] = qT[s * 8 + tq][r + 8];
                a[2] = qT[s * 8 + tq + 4][r];
                a[3] = qT[s * 8 + tq + 4][r + 8];
                mma_tf32(dreg[ma], a, b);
            }
        }
        #pragma unroll
        for (int ma = 0; ma < 4; ma++) {
            int r0 = ma * 16 + tg;
            int r1 = r0 + 8;
            float vals[2][2] = {{dreg[ma][0], dreg[ma][1]}, {dreg[ma][2], dreg[ma][3]}};
            float rmax[2];
            #pragma unroll
            for (int h = 0; h < 2; h++) {
                int i = h ? r1 : r0;
                float cm = NEG;
                if (i < PP) {
                    int iy = i / PW, ix = i % PW;
                    #pragma unroll
                    for (int jj = 0; jj < 2; jj++) {
                        int j = j0 + jj;
                        float val = NEG;
                        if (j < PP) {
                            int jy = j / PW, jx = j % PW;
                            val = vals[h][jj] * scale + poss[(jy - iy + 6) * 13 + (jx - ix + 6)];
                            if (m_ul && ((iy >= 4) != (jy >= 4))) val = NEG;
                            if (m_lr && ((ix >= 4) != (jx >= 4))) val = NEG;
                            dotsT[j][i] = __float_as_uint(val);
                            cm = fmaxf(cm, val);
                        }
                    }
                }
                rmax[h] = cm;
            }
            #pragma unroll
            for (int h = 0; h < 2; h++) {
                rmax[h] = fmaxf(rmax[h], __shfl_xor_sync(0xffffffffu, rmax[h], 1));
                rmax[h] = fmaxf(rmax[h], __shfl_xor_sync(0xffffffffu, rmax[h], 2));
            }
            if (tq == 0) {
                if (r0 < PP) cpart[r0][na] = rmax[0];
                if (r1 < PP) cpart[r1][na] = rmax[1];
            }
        }
    }
    __syncthreads();

    if (tid < PP) {
        int i = tid;
        float mx = cpart[i][0];
        #pragma unroll
        for (int c = 1; c < 7; c++) mx = fmaxf(mx, cpart[i][c]);
        float s = 0.f;
        for (int j = 0; j < PP; j++) {
            float e = __expf(__uint_as_float(dotsT[j][i]) - mx);
            dotsT[j][i] = f2tf32(e);
            s += e;
        }
        rowinv[i] = 1.0f / s;
    }
    __syncthreads();

    {
        const int na = wid & 3;
        const int mh = wid >> 2;
        uint32_t* ob = g_att32 + (size_t)(bi * NWIN + w) * PP * INNER + head * DH;
        float dreg[2][4] = {};
        #pragma unroll
        for (int t = 0; t < 7; t++) {
            uint32_t b[2];
            b[0] = v[t * 8 + tq][na * 8 + tg];
            b[1] = v[t * 8 + tq + 4][na * 8 + tg];
            #pragma unroll
            for (int mi = 0; mi < 2; mi++) {
                int r = (mh * 2 + mi) * 16 + tg;
                uint32_t a[4];
                a[0] = dotsT[t * 8 + tq][r];
                a[1] = dotsT[t * 8 + tq][r + 8];
                a[2] = dotsT[t * 8 + tq + 4][r];
                a[3] = dotsT[t * 8 + tq + 4][r + 8];
                mma_tf32(dreg[mi], a, b);
            }
        }
        #pragma unroll
        for (int mi = 0; mi < 2; mi++) {
            int r0 = (mh * 2 + mi) * 16 + tg;
            int dcol = na * 8 + 2 * tq;
            if (r0 < PP) {
                float inv = rowinv[r0];
                uint2 o;
                o.x = f2tf32(dreg[mi][0] * inv);
                o.y = f2tf32(dreg[mi][1] * inv);
                *(uint2*)&ob[(size_t)r0 * INNER + dcol] = o;
            }
            int r1 = r0 + 8;
            if (r1 < PP) {
                float inv = rowinv[r1];
                uint2 o;
                o.x = f2tf32(dreg[mi][2] * inv);
                o.y = f2tf32(dreg[mi][3] * inv);
                *(uint2*)&ob[(size_t)r1 * INNER + dcol] = o;
            }
        }
    }

    float* ao = attn_out + (size_t)bid * (PP * PP);
    for (int idx = tid; idx < PP * PP; idx += 256) {
        int i = idx / PP, j = idx % PP;
        ao[idx] = __uint_as_float(dotsT[j][i]) * rowinv[i];
    }
}

// ---------------------------------------------------------------------------
// Kernel 3: out GEMM (R14-measured version: 128 threads, 4 warps of 64x64)
// ---------------------------------------------------------------------------
__global__ void __launch_bounds__(128, 2) out_gemm(const float* __restrict__ bout,
                                                   float* __restrict__ out) {
    __shared__ union U {
        struct { uint32_t As[2][16][PADW]; uint32_t Bs[2][16][PADW]; } mm;
        float sbuf[128][65];
        __device__ U() {}
    } sh;
    __shared__ int   rowoff[128];
    __shared__ float bout_s[128];

    const int m0  = blockIdx.y * 128;
    const int n0  = blockIdx.x * 128;
    const int tid = threadIdx.x;

    rowoff[tid] = row_to_off(m0 + tid);
    bout_s[tid] = bout[n0 + tid];

    const int lane = tid & 31;
    const int wid  = tid >> 5;
    const int mb   = (wid & 1) * 64;
    const int half_of_warp = wid >> 1;
    const int tg   = lane >> 2;
    const int tq   = lane & 3;

    const uint32_t* arow = g_att32 + (size_t)(m0 + tid) * INNER;
    const uint32_t* brow = g_wout32 + n0 + tid;

    float d[4][8][4] = {};
    uint32_t a_reg[16], b_reg[16];

    #pragma unroll
    for (int i = 0; i < 4; i++)
        *(uint4*)&a_reg[4 * i] = *(const uint4*)(arow + 4 * i);
    #pragma unroll
    for (int i = 0; i < 16; i++) b_reg[i] = brow[i * DIM];
    #pragma unroll
    for (int i = 0; i < 16; i++) {
        sh.mm.As[0][i][tid] = a_reg[i];
        sh.mm.Bs[0][i][tid] = b_reg[i];
    }
    __syncthreads();

    for (int c = 0; c < 16; c++) {
        const int cur = c & 1;
        if (c < 15) {
            const int kb = (c + 1) * 16;
            #pragma unroll
            for (int i = 0; i < 4; i++)
                *(uint4*)&a_reg[4 * i] = *(const uint4*)(arow + kb + 4 * i);
            #pragma unroll
            for (int i = 0; i < 16; i++) b_reg[i] = brow[(kb + i) * DIM];
        }
        #pragma unroll
        for (int s = 0; s < 2; s++) {
            uint32_t a[4][4], b[8][2];
            #pragma unroll
            for (int am = 0; am < 4; am++) {
                int r = mb + am * 16 + tg;
                a[am][0] = sh.mm.As[cur][s * 8 + tq][r];
                a[am][1] = sh.mm.As[cur][s * 8 + tq][r + 8];
                a[am][2] = sh.mm.As[cur][s * 8 + tq + 4][r];
                a[am][3] = sh.mm.As[cur][s * 8 + tq + 4][r + 8];
            }
            #pragma unroll
            for (int an = 0; an < 8; an++) {
                int cc = half_of_warp * 64 + an * 8 + tg;
                b[an][0] = sh.mm.Bs[cur][s * 8 + tq][cc];
                b[an][1] = sh.mm.Bs[cur][s * 8 + tq + 4][cc];
            }
            #pragma unroll
            for (int am = 0; am < 4; am++)
                #pragma unroll
                for (int an = 0; an < 8; an++)
                    mma_tf32(d[am][an], a[am], b[an]);
        }
        if (c < 15) {
            const int nxt = cur ^ 1;
            #pragma unroll
            for (int i = 0; i < 16; i++) {
                sh.mm.As[nxt][i][tid] = a_reg[i];
                sh.mm.Bs[nxt][i][tid] = b_reg[i];
            }
        }
        __syncthreads();
    }

    #pragma unroll
    for (int half = 0; half < 2; half++) {
        if (half_of_warp == half) {
            #pragma unroll
            for (int am = 0; am < 4; am++) {
                int r0 = mb + am * 16 + tg;
                #pragma unroll
                for (int an = 0; an < 8; an++) {
                    int c = an * 8 + 2 * tq;
                    sh.sbuf[r0][c]         = d[am][an][0];
                    sh.sbuf[r0][c + 1]     = d[am][an][1];
                    sh.sbuf[r0 + 8][c]     = d[am][an][2];
                    sh.sbuf[r0 + 8][c + 1] = d[am][an][3];
                }
            }
        }
        __syncthreads();
        #pragma unroll
        for (int it = 0; it < 64; it++) {
            int flat = it * 128 + tid;
            int m = flat & 127;
            int c = flat >> 7;
            int col = half * 64 + c;
            out[rowoff[m] + (n0 + col) * SP] = sh.sbuf[m][c] + bout_s[col];
        }
        __syncthreads();
    }
}

// ---------------------------------------------------------------------------
extern "C" void kernel_launch(void* const* d_in, const int* in_sizes, int n_in,
                              void* d_out, int out_size) {
    const float* x    = (const float*)d_in[0];
    const float* pos  = (const float*)d_in[1];
    const float* wqkv = (const float*)d_in[2];
    const float* wout = (const float*)d_in[3];
    const float* bout = (const float*)d_in[4];

    float* out      = (float*)d_out;
    float* attn_out = out + (size_t)BATCH * DIM * SP;

    prep_w<<<256, 256>>>(wqkv, wout);

    dim3 g1(QKV_N / 128, M_TOTAL / 128);
    qkv_gemm<<<g1, 128>>>(x);

    attn_kernel<<<BATCH * NWIN * HEADS, 256>>>(pos, attn_out);

    dim3 g3(DIM / 128, M_TOTAL / 128);
    out_gemm<<<g3, 128>>>(bout, out);
}